// round 7
// baseline (speedup 1.0000x reference)
#include <cuda_runtime.h>

#define WIDTH  1024
#define HEIGHT 1024
#define RPB    8          // rows per block-strip (must divide HEIGHT)

__device__ float        g_partials[65536];
__device__ unsigned int g_count = 0;   // self-resetting; 0 before every launch

struct RowData {
    float4 v;      // 4 target values at columns c..c+3
    float  hl, hr; // column halo (c-1 clamped, c+4 clamped)
};

__device__ __forceinline__ RowData load_row(const float* __restrict__ r,
                                            int c, int cl, int cr)
{
    RowData d;
    d.v  = *reinterpret_cast<const float4*>(r + c);
    d.hl = r[cl];
    d.hr = r[cr];
    return d;
}

// EXACT R2 streaming body (proven 6.46 TB/s): each block handles an 8-row
// strip of one image; the 3-row target window rolls through registers.
// Binary-mask morphology: boundary <=> clamped 3x3 window sum in (0,9).
// BCE with t in {0,1}: bce = -log(t ? p : 1-p)  -> one __logf per pixel.
// The LAST block to finish does the deterministic final reduction in-kernel,
// eliminating the ~8us fixed overhead of a second single-block launch.
__global__ void __launch_bounds__(256)
loss_kernel(const float* __restrict__ pred, const float* __restrict__ tgt,
            float* __restrict__ out, int n_strips, double inv_n)
{
    const int strip = blockIdx.x;
    const int row0  = strip * RPB;
    const int y0    = row0 & (HEIGHT - 1);   // strip never crosses images

    const int c  = threadIdx.x << 2;
    const int cl = (c == 0) ? 0 : c - 1;
    const int cr = (c + 4 >= WIDTH) ? (WIDTH - 1) : (c + 4);

    const float* tbase = tgt  + (size_t)row0 * WIDTH;
    const float* pbase = pred + (size_t)row0 * WIDTH;

    RowData a_prev = load_row((y0 == 0) ? tbase : tbase - WIDTH, c, cl, cr);
    RowData a_cur  = load_row(tbase, c, cl, cr);

    float acc = 0.0f;    // accumulates +w*log(arg); negated at the end

    #pragma unroll
    for (int i = 0; i < RPB; i++) {
        const int y = y0 + i;
        const float* trow_next = (y == HEIGHT - 1) ? tbase + (size_t)i * WIDTH
                                                   : tbase + (size_t)(i + 1) * WIDTH;
        const RowData a_next = load_row(trow_next, c, cl, cr);
        const float4  p = *reinterpret_cast<const float4*>(
                              pbase + (size_t)i * WIDTH + c);

        const float v0 = a_prev.v.x + a_cur.v.x + a_next.v.x;
        const float v1 = a_prev.v.y + a_cur.v.y + a_next.v.y;
        const float v2 = a_prev.v.z + a_cur.v.z + a_next.v.z;
        const float v3 = a_prev.v.w + a_cur.v.w + a_next.v.w;
        const float vl = a_prev.hl  + a_cur.hl  + a_next.hl;
        const float vr = a_prev.hr  + a_cur.hr  + a_next.hr;

        const float s0 = vl + v0 + v1;
        const float s1 = v0 + v1 + v2;
        const float s2 = v1 + v2 + v3;
        const float s3 = v2 + v3 + vr;

#define PIX(S, T, P)                                                      \
        do {                                                              \
            const float arg = ((T) > 0.5f) ? (P) : (1.0f - (P));          \
            const float w   = ((S) > 0.5f && (S) < 8.5f) ? 3.0f : 1.0f;   \
            acc = fmaf(w, __logf(arg), acc);                              \
        } while (0)

        PIX(s0, a_cur.v.x, p.x);
        PIX(s1, a_cur.v.y, p.y);
        PIX(s2, a_cur.v.z, p.z);
        PIX(s3, a_cur.v.w, p.w);
#undef PIX

        a_prev = a_cur;
        a_cur  = a_next;
    }

    // Block reduction: warp shuffle, then 8 warp leaders through smem.
    #pragma unroll
    for (int o = 16; o > 0; o >>= 1)
        acc += __shfl_xor_sync(0xffffffffu, acc, o);

    __shared__ float sacc[8];
    __shared__ bool  s_last;
    const int wid  = threadIdx.x >> 5;
    const int lane = threadIdx.x & 31;
    if (lane == 0) sacc[wid] = acc;
    __syncthreads();

    if (threadIdx.x == 0) {
        float s = 0.0f;
        #pragma unroll
        for (int i = 0; i < 8; i++) s += sacc[i];
        g_partials[strip] = -s;
        __threadfence();                       // publish partial before count
        const unsigned int old = atomicAdd(&g_count, 1u);
        s_last = (old == (unsigned int)(n_strips - 1));
    }
    __syncthreads();

    if (s_last) {
        // Deterministic fixed-order double reduction of all partials
        // (L2-resident, ~16KB). n_strips is a multiple of 1024 here
        // (4096 nominal), so each thread sums a fixed strided set.
        const int n4 = n_strips >> 2;
        double s = 0.0;
        for (int i = threadIdx.x; i < n4; i += 256) {
            const float4 v = reinterpret_cast<const float4*>(g_partials)[i];
            s += (double)v.x + (double)v.y + (double)v.z + (double)v.w;
        }

        // Warp-level double reduction, then 8 leaders.
        #pragma unroll
        for (int o = 16; o > 0; o >>= 1)
            s += __shfl_xor_sync(0xffffffffu, s, o);

        __shared__ double sd[8];
        if (lane == 0) sd[wid] = s;
        __syncthreads();
        if (threadIdx.x == 0) {
            double t = 0.0;
            #pragma unroll
            for (int i = 0; i < 8; i++) t += sd[i];
            out[0]  = (float)(t * inv_n);
            g_count = 0;                       // reset for the next graph replay
        }
    }
}

extern "C" void kernel_launch(void* const* d_in, const int* in_sizes, int n_in,
                              void* d_out, int out_size)
{
    const float* pred = (const float*)d_in[0];
    const float* tgt  = (const float*)d_in[1];
    const int n      = in_sizes[0];        // B*1*H*W
    const int rows   = n / WIDTH;          // B*H
    const int strips = rows / RPB;

    loss_kernel<<<strips, 256>>>(pred, tgt, (float*)d_out, strips,
                                 1.0 / (double)n);
}

// round 8
// speedup vs baseline: 1.0390x; 1.0390x over previous
#include <cuda_runtime.h>

#define WIDTH  1024
#define HEIGHT 1024
#define RPB    8          // rows per block-strip (must divide HEIGHT)

// One partial per block-strip. 32*1024/8 = 4096 for the nominal shape.
__device__ float g_partials[65536];

struct RowData {
    float4 v;      // 4 target values at columns c..c+3
    float  hl, hr; // column halo (c-1 clamped, c+4 clamped)
};

__device__ __forceinline__ RowData load_row(const float* __restrict__ r,
                                            int c, int cl, int cr)
{
    RowData d;
    d.v  = *reinterpret_cast<const float4*>(r + c);
    d.hl = r[cl];
    d.hr = r[cr];
    return d;
}

// R2 streaming body + SOFTWARE PIPELINE: the next iteration's target row and
// pred row are prefetched into registers before computing the current
// iteration, doubling per-thread memory-level parallelism (the profiles show
// latency-bound behavior: DRAM 65%, issue 40%).
// Binary-mask morphology: boundary <=> clamped 3x3 window sum in (0,9).
// BCE with t in {0,1}: bce = -log(t ? p : 1-p)  -> one __logf per pixel.
__global__ void __launch_bounds__(256)
loss_kernel(const float* __restrict__ pred, const float* __restrict__ tgt)
{
    const int strip = blockIdx.x;
    const int row0  = strip * RPB;
    const int y0    = row0 & (HEIGHT - 1);   // strip never crosses images

    const int c  = threadIdx.x << 2;
    const int cl = (c == 0) ? 0 : c - 1;
    const int cr = (c + 4 >= WIDTH) ? (WIDTH - 1) : (c + 4);

    const float* tbase = tgt  + (size_t)row0 * WIDTH;
    const float* pbase = pred + (size_t)row0 * WIDTH;

    // Prime: rows y0-1 (clamped), y0, and prefetch row y0+1 + pred row y0.
    RowData a_prev = load_row((y0 == 0) ? tbase : tbase - WIDTH, c, cl, cr);
    RowData a_cur  = load_row(tbase, c, cl, cr);
    RowData a_nx   = load_row(tbase + WIDTH, c, cl, cr);       // row y0+1 (safe: RPB>=2)
    float4  p_nx   = *reinterpret_cast<const float4*>(pbase + c);

    float acc = 0.0f;    // accumulates +w*log(arg); negated at the end

    #pragma unroll
    for (int i = 0; i < RPB; i++) {
        const RowData a_next = a_nx;
        const float4  p      = p_nx;

        if (i + 1 < RPB) {
            // Prefetch iteration i+1: target row y0+i+2 (clamped) + pred row i+1.
            const int off = (y0 + i + 2 > HEIGHT - 1) ? (HEIGHT - 1 - y0) : (i + 2);
            a_nx = load_row(tbase + (size_t)off * WIDTH, c, cl, cr);
            p_nx = *reinterpret_cast<const float4*>(pbase + (size_t)(i + 1) * WIDTH + c);
        }

        const float v0 = a_prev.v.x + a_cur.v.x + a_next.v.x;
        const float v1 = a_prev.v.y + a_cur.v.y + a_next.v.y;
        const float v2 = a_prev.v.z + a_cur.v.z + a_next.v.z;
        const float v3 = a_prev.v.w + a_cur.v.w + a_next.v.w;
        const float vl = a_prev.hl  + a_cur.hl  + a_next.hl;
        const float vr = a_prev.hr  + a_cur.hr  + a_next.hr;

        const float s0 = vl + v0 + v1;
        const float s1 = v0 + v1 + v2;
        const float s2 = v1 + v2 + v3;
        const float s3 = v2 + v3 + vr;

#define PIX(S, T, P)                                                      \
        do {                                                              \
            const float arg = ((T) > 0.5f) ? (P) : (1.0f - (P));          \
            const float w   = ((S) > 0.5f && (S) < 8.5f) ? 3.0f : 1.0f;   \
            acc = fmaf(w, __logf(arg), acc);                              \
        } while (0)

        PIX(s0, a_cur.v.x, p.x);
        PIX(s1, a_cur.v.y, p.y);
        PIX(s2, a_cur.v.z, p.z);
        PIX(s3, a_cur.v.w, p.w);
#undef PIX

        a_prev = a_cur;
        a_cur  = a_next;
    }

    // Block reduction: warp shuffle, then 8 warp leaders through smem.
    #pragma unroll
    for (int o = 16; o > 0; o >>= 1)
        acc += __shfl_xor_sync(0xffffffffu, acc, o);

    __shared__ float sacc[8];
    const int wid  = threadIdx.x >> 5;
    const int lane = threadIdx.x & 31;
    if (lane == 0) sacc[wid] = acc;
    __syncthreads();
    if (threadIdx.x == 0) {
        float s = 0.0f;
        #pragma unroll
        for (int i = 0; i < 8; i++) s += sacc[i];
        g_partials[strip] = -s;
    }
}

// Deterministic final reduction (double precision), vectorized loads.
__global__ void __launch_bounds__(256)
finalize_kernel(float* __restrict__ out, int n_part, double inv_n)
{
    const int n4 = n_part >> 2;   // n_part divisible by 4
    double s0 = 0.0, s1 = 0.0;
    for (int i = threadIdx.x; i < n4; i += 256) {
        const float4 v = reinterpret_cast<const float4*>(g_partials)[i];
        s0 += (double)v.x + (double)v.y;
        s1 += (double)v.z + (double)v.w;
    }
    double s = s0 + s1;

    __shared__ double sd[256];
    sd[threadIdx.x] = s;
    __syncthreads();
    #pragma unroll
    for (int o = 128; o > 0; o >>= 1) {
        if (threadIdx.x < o) sd[threadIdx.x] += sd[threadIdx.x + o];
        __syncthreads();
    }
    if (threadIdx.x == 0)
        out[0] = (float)(sd[0] * inv_n);
}

extern "C" void kernel_launch(void* const* d_in, const int* in_sizes, int n_in,
                              void* d_out, int out_size)
{
    const float* pred = (const float*)d_in[0];
    const float* tgt  = (const float*)d_in[1];
    const int n      = in_sizes[0];        // B*1*H*W
    const int rows   = n / WIDTH;          // B*H
    const int strips = rows / RPB;

    loss_kernel<<<strips, 256>>>(pred, tgt);
    finalize_kernel<<<1, 256>>>((float*)d_out, strips, 1.0 / (double)n);
}